// round 1
// baseline (speedup 1.0000x reference)
#include <cuda_runtime.h>
#include <cuda_bf16.h>

#define NS   150
#define BATCH 32
#define DIN  1024
#define DH   512
#define DOUT 256

// -------------------- scratch (no cudaMalloc allowed) --------------------
__device__ float g_W1[NS * DH * DIN];    // 314.6 MB
__device__ float g_B1[NS * DH];
__device__ float g_W2[NS * DOUT * DH];   // 78.6 MB
__device__ float g_B2[NS * DOUT];
__device__ float g_H [NS * BATCH * DH];  // 9.8 MB

// -------------------- threefry2x32 (JAX-exact) --------------------
__device__ __forceinline__ void tf2x32(unsigned k0, unsigned k1,
                                       unsigned x0, unsigned x1,
                                       unsigned& o0, unsigned& o1)
{
    const unsigned ks2 = k0 ^ k1 ^ 0x1BD11BDAu;
    x0 += k0; x1 += k1;
#define TF_RND(r) { x0 += x1; x1 = __funnelshift_l(x1, x1, (r)); x1 ^= x0; }
    TF_RND(13) TF_RND(15) TF_RND(26) TF_RND(6)   x0 += k1;  x1 += ks2 + 1u;
    TF_RND(17) TF_RND(29) TF_RND(16) TF_RND(24)  x0 += ks2; x1 += k0  + 2u;
    TF_RND(13) TF_RND(15) TF_RND(26) TF_RND(6)   x0 += k0;  x1 += k1  + 3u;
    TF_RND(17) TF_RND(29) TF_RND(16) TF_RND(24)  x0 += k1;  x1 += ks2 + 4u;
    TF_RND(13) TF_RND(15) TF_RND(26) TF_RND(6)   x0 += ks2; x1 += k0  + 5u;
#undef TF_RND
    o0 = x0; o1 = x1;
}

// JAX partitionable random_bits (32-bit): counter e (hi=0, lo=e), xor-fold.
// Then uniform(lo=nextafter(-1,0), hi=1) and XLA ErfInv32, scaled by sqrt(2).
__device__ __forceinline__ float tf_normal(unsigned k0, unsigned k1, unsigned e)
{
    unsigned o0, o1;
    tf2x32(k0, k1, 0u, e, o0, o1);
    unsigned bits = o0 ^ o1;

    float f = __uint_as_float((bits >> 9) | 0x3f800000u) - 1.0f;   // [0,1)
    float x = fmaf(f, 2.0f, -0.99999994f);                          // [lo, ~1)

    float w = -log1pf(-x * x);
    float p;
    if (w < 5.0f) {
        w -= 2.5f;
        p = 2.81022636e-08f;
        p = fmaf(p, w, 3.43273939e-07f);
        p = fmaf(p, w, -3.5233877e-06f);
        p = fmaf(p, w, -4.39150654e-06f);
        p = fmaf(p, w, 0.00021858087f);
        p = fmaf(p, w, -0.00125372503f);
        p = fmaf(p, w, -0.00417768164f);
        p = fmaf(p, w, 0.246640727f);
        p = fmaf(p, w, 1.50140941f);
    } else {
        w = sqrtf(w) - 3.0f;
        p = -0.000200214257f;
        p = fmaf(p, w, 0.000100950558f);
        p = fmaf(p, w, 0.00134934322f);
        p = fmaf(p, w, -0.00367342844f);
        p = fmaf(p, w, 0.00573950773f);
        p = fmaf(p, w, -0.0076224613f);
        p = fmaf(p, w, 0.00943887047f);
        p = fmaf(p, w, 1.00167406f);
        p = fmaf(p, w, 2.83297682f);
    }
    return 1.41421356237f * (p * x);
}

// -------------------- weight-sample generation --------------------
// out[e] = mu[e % paramSize] + eps(e) * exp(v[e % paramSize]); 2 elems/thread.
__global__ __launch_bounds__(256) void gen_kernel(
    unsigned k0, unsigned k1,
    const float* __restrict__ mu, const float* __restrict__ v,
    float* __restrict__ out, int size, int paramSize)
{
    unsigned pair = blockIdx.x * 256u + threadIdx.x;
    unsigned e = pair * 2u;
    if ((int)e >= size) return;

    float r0 = tf_normal(k0, k1, e);
    float r1 = tf_normal(k0, k1, e + 1u);

    int p = (int)(e % (unsigned)paramSize);     // e even, paramSize even
    float2 m  = *reinterpret_cast<const float2*>(mu + p);
    float2 vv = *reinterpret_cast<const float2*>(v  + p);
    float2 o;
    o.x = fmaf(r0, expf(vv.x), m.x);
    o.y = fmaf(r1, expf(vv.y), m.y);
    *reinterpret_cast<float2*>(out + e) = o;
}

// -------------------- batched skinny GEMM --------------------
// Out[n][b][c] = (RELU?)( bias[n][c] + sum_k X[n][b][k] * W[n][c][k] )
// block = (n, 128-wide c tile), 128 threads, thread = 4 b x 8 c accumulators.
template<int K, int N, bool RELU>
__global__ __launch_bounds__(128) void gemm_kernel(
    const float* __restrict__ X, long long xStride,
    const float* __restrict__ W, const float* __restrict__ bias,
    float* __restrict__ Out)
{
    const int n  = blockIdx.x;
    const int c0 = blockIdx.y * 128;
    const float* Xn = X + (long long)n * xStride;
    const float* Wn = W + ((long long)n * N + c0) * K;

    __shared__ float xs[32][33];    // [k][b], padded: conflict-free
    __shared__ float ws[32][129];   // [k][c], padded: conflict-free

    const int tid = threadIdx.x;
    const int b0 = (tid & 7) * 4;   // 4 batch rows
    const int h0 = (tid >> 3) * 8;  // 8 output cols

    float acc[4][8];
#pragma unroll
    for (int i = 0; i < 4; i++)
#pragma unroll
        for (int j = 0; j < 8; j++) acc[i][j] = 0.0f;

    for (int k0 = 0; k0 < K; k0 += 32) {
        // X tile: 32 rows x 8 float4 (256 float4 / 128 thr = 2 each)
        int idx = tid;
#pragma unroll
        for (int t = 0; t < 2; t++) {
            int r = idx >> 3, c4 = idx & 7;
            float4 xv = *reinterpret_cast<const float4*>(Xn + r * K + k0 + c4 * 4);
            xs[c4 * 4 + 0][r] = xv.x; xs[c4 * 4 + 1][r] = xv.y;
            xs[c4 * 4 + 2][r] = xv.z; xs[c4 * 4 + 3][r] = xv.w;
            idx += 128;
        }
        // W tile: 128 rows x 8 float4 (1024 float4 / 128 thr = 8 each)
        idx = tid;
#pragma unroll
        for (int t = 0; t < 8; t++) {
            int r = idx >> 3, c4 = idx & 7;
            float4 wv = *reinterpret_cast<const float4*>(Wn + r * K + k0 + c4 * 4);
            ws[c4 * 4 + 0][r] = wv.x; ws[c4 * 4 + 1][r] = wv.y;
            ws[c4 * 4 + 2][r] = wv.z; ws[c4 * 4 + 3][r] = wv.w;
            idx += 128;
        }
        __syncthreads();
#pragma unroll 8
        for (int kk = 0; kk < 32; kk++) {
            float xv[4], wv[8];
#pragma unroll
            for (int i = 0; i < 4; i++) xv[i] = xs[kk][b0 + i];
#pragma unroll
            for (int j = 0; j < 8; j++) wv[j] = ws[kk][h0 + j];
#pragma unroll
            for (int i = 0; i < 4; i++)
#pragma unroll
                for (int j = 0; j < 8; j++)
                    acc[i][j] = fmaf(xv[i], wv[j], acc[i][j]);
        }
        __syncthreads();
    }

#pragma unroll
    for (int j = 0; j < 8; j++) {
        float bj = bias[(long long)n * N + c0 + h0 + j];
#pragma unroll
        for (int i = 0; i < 4; i++) {
            float r = acc[i][j] + bj;
            if (RELU) r = fmaxf(r, 0.0f);
            Out[((long long)n * BATCH + (b0 + i)) * N + c0 + h0 + j] = r;
        }
    }
}

// -------------------- host-side threefry for subkey derivation --------------------
static inline unsigned h_rotl(unsigned x, int r) { return (x << r) | (x >> (32 - r)); }
static void h_tf2x32(unsigned k0, unsigned k1, unsigned x0, unsigned x1,
                     unsigned& o0, unsigned& o1)
{
    const unsigned ks2 = k0 ^ k1 ^ 0x1BD11BDAu;
    x0 += k0; x1 += k1;
    static const int R[2][4] = {{13, 15, 26, 6}, {17, 29, 16, 24}};
    const unsigned ks[3] = {k0, k1, ks2};
    for (int g = 0; g < 5; g++) {
        for (int r = 0; r < 4; r++) {
            x0 += x1; x1 = h_rotl(x1, R[g & 1][r]); x1 ^= x0;
        }
        x0 += ks[(g + 1) % 3];
        x1 += ks[(g + 2) % 3] + (unsigned)(g + 1);
    }
    o0 = x0; o1 = x1;
}

extern "C" void kernel_launch(void* const* d_in, const int* in_sizes, int n_in,
                              void* d_out, int out_size)
{
    const float* x    = (const float*)d_in[0];
    const float* muW1 = (const float*)d_in[1];
    const float* mub1 = (const float*)d_in[2];
    const float* muW2 = (const float*)d_in[3];
    const float* mub2 = (const float*)d_in[4];
    const float* vW1  = (const float*)d_in[5];
    const float* vb1  = (const float*)d_in[6];
    const float* vW2  = (const float*)d_in[7];
    const float* vb2  = (const float*)d_in[8];
    float* out = (float*)d_out;

    // jax.random.key(42) == (0, 42); split(key, 4) under partitionable threefry:
    // child i = threefry2x32((0,42), (hi=0, lo=i)) stacked as (out0, out1).
    unsigned keys[4][2];
    for (unsigned i = 0; i < 4; i++)
        h_tf2x32(0u, 42u, 0u, i, keys[i][0], keys[i][1]);

    float *W1, *B1, *W2, *B2, *H;
    cudaGetSymbolAddress((void**)&W1, g_W1);
    cudaGetSymbolAddress((void**)&B1, g_B1);
    cudaGetSymbolAddress((void**)&W2, g_W2);
    cudaGetSymbolAddress((void**)&B2, g_B2);
    cudaGetSymbolAddress((void**)&H,  g_H);

    // eW1: 78,643,200 elems; eb1: 76,800; eW2: 19,660,800; eb2: 38,400
    gen_kernel<<<(NS * DH * DIN) / 512, 256>>>(keys[0][0], keys[0][1], muW1, vW1, W1,
                                               NS * DH * DIN, DH * DIN);
    gen_kernel<<<(NS * DH) / 512, 256>>>(keys[1][0], keys[1][1], mub1, vb1, B1,
                                         NS * DH, DH);
    gen_kernel<<<(NS * DOUT * DH) / 512, 256>>>(keys[2][0], keys[2][1], muW2, vW2, W2,
                                                NS * DOUT * DH, DOUT * DH);
    gen_kernel<<<(NS * DOUT) / 512, 256>>>(keys[3][0], keys[3][1], mub2, vb2, B2,
                                           NS * DOUT, DOUT);

    // h = relu(x @ W1^T + b1)   [150,32,512]
    gemm_kernel<DIN, DH, true><<<dim3(NS, DH / 128), 128>>>(x, 0LL, W1, B1, H);
    // y = h @ W2^T + b2         [150,32,256]
    gemm_kernel<DH, DOUT, false><<<dim3(NS, DOUT / 128), 128>>>(H, (long long)(BATCH * DH),
                                                                W2, B2, out);
}

// round 2
// speedup vs baseline: 1.0119x; 1.0119x over previous
#include <cuda_runtime.h>
#include <cuda_bf16.h>

#define NS    150
#define BATCH 32
#define DIN   1024
#define DH    512
#define DOUT  256

// -------------------- scratch (no cudaMalloc allowed) --------------------
__device__ float g_sW1[DH * DIN];        // exp(v_W1), sample-invariant
__device__ float g_sW2[DOUT * DH];       // exp(v_W2)
__device__ float g_H[NS * BATCH * DH];   // hidden activations

// -------------------- threefry2x32 (JAX-exact, frozen) --------------------
__device__ __forceinline__ void tf2x32(unsigned k0, unsigned k1,
                                       unsigned x0, unsigned x1,
                                       unsigned& o0, unsigned& o1)
{
    const unsigned ks2 = k0 ^ k1 ^ 0x1BD11BDAu;
    x0 += k0; x1 += k1;
#define TF_RND(r) { x0 += x1; x1 = __funnelshift_l(x1, x1, (r)); x1 ^= x0; }
    TF_RND(13) TF_RND(15) TF_RND(26) TF_RND(6)   x0 += k1;  x1 += ks2 + 1u;
    TF_RND(17) TF_RND(29) TF_RND(16) TF_RND(24)  x0 += ks2; x1 += k0  + 2u;
    TF_RND(13) TF_RND(15) TF_RND(26) TF_RND(6)   x0 += k0;  x1 += k1  + 3u;
    TF_RND(17) TF_RND(29) TF_RND(16) TF_RND(24)  x0 += k1;  x1 += ks2 + 4u;
    TF_RND(13) TF_RND(15) TF_RND(26) TF_RND(6)   x0 += ks2; x1 += k0  + 5u;
#undef TF_RND
    o0 = x0; o1 = x1;
}

// JAX partitionable random_bits: counter (0, e), xor-fold; uniform map + XLA ErfInv32.
__device__ __forceinline__ float tf_normal(unsigned k0, unsigned k1, unsigned e)
{
    unsigned o0, o1;
    tf2x32(k0, k1, 0u, e, o0, o1);
    unsigned bits = o0 ^ o1;

    float f = __uint_as_float((bits >> 9) | 0x3f800000u) - 1.0f;
    float x = fmaf(f, 2.0f, -0.99999994f);

    float w = -log1pf(-x * x);
    float p;
    if (w < 5.0f) {
        w -= 2.5f;
        p = 2.81022636e-08f;
        p = fmaf(p, w, 3.43273939e-07f);
        p = fmaf(p, w, -3.5233877e-06f);
        p = fmaf(p, w, -4.39150654e-06f);
        p = fmaf(p, w, 0.00021858087f);
        p = fmaf(p, w, -0.00125372503f);
        p = fmaf(p, w, -0.00417768164f);
        p = fmaf(p, w, 0.246640727f);
        p = fmaf(p, w, 1.50140941f);
    } else {
        w = sqrtf(w) - 3.0f;
        p = -0.000200214257f;
        p = fmaf(p, w, 0.000100950558f);
        p = fmaf(p, w, 0.00134934322f);
        p = fmaf(p, w, -0.00367342844f);
        p = fmaf(p, w, 0.00573950773f);
        p = fmaf(p, w, -0.0076224613f);
        p = fmaf(p, w, 0.00943887047f);
        p = fmaf(p, w, 1.00167406f);
        p = fmaf(p, w, 2.83297682f);
    }
    return 1.41421356237f * (p * x);
}

// -------------------- packed f32x2 helpers (sm_100+ PTX) --------------------
__device__ __forceinline__ unsigned long long pack_dup(float a)
{
    unsigned long long d;
    unsigned r = __float_as_uint(a);
    asm("mov.b64 %0, {%1, %1};" : "=l"(d) : "r"(r));
    return d;
}
__device__ __forceinline__ unsigned long long ffma2(unsigned long long a,
                                                    unsigned long long b,
                                                    unsigned long long c)
{
    unsigned long long d;
    asm("fma.rn.f32x2 %0, %1, %2, %3;" : "=l"(d) : "l"(a), "l"(b), "l"(c));
    return d;
}
__device__ __forceinline__ float2 unpack2(unsigned long long d)
{
    unsigned lo, hi;
    asm("mov.b64 {%0, %1}, %2;" : "=r"(lo), "=r"(hi) : "l"(d));
    return make_float2(__uint_as_float(lo), __uint_as_float(hi));
}

// -------------------- exp(v_W) precompute (bit-identical expf) --------------------
__global__ __launch_bounds__(256) void prep_kernel(const float* __restrict__ vW1,
                                                   const float* __restrict__ vW2)
{
    int i = blockIdx.x * 256 + threadIdx.x;
    if (i < DH * DIN)  g_sW1[i] = expf(vW1[i]);
    if (i < DOUT * DH) g_sW2[i] = expf(vW2[i]);
}

// -------------------- fused sample-and-GEMM --------------------
// Out[n][b][c] = act( bias_n[c] + sum_k X[n][b][k] * (mu[c][k] + eps(n,c,k)*s[c][k]) )
// block = (n, 128-wide c tile), 128 threads, thread = 4 b x 8 c (4 f32x2 pairs).
template<int K, int N, bool RELU>
__global__ __launch_bounds__(128) void fused_kernel(
    const float* __restrict__ X, long long xStride,
    const float* __restrict__ mu, const float* __restrict__ s,
    const float* __restrict__ mub, const float* __restrict__ vb,
    float* __restrict__ Out,
    unsigned wk0, unsigned wk1, unsigned bk0, unsigned bk1)
{
    const int n  = blockIdx.x;
    const int c0 = blockIdx.y * 128;
    const float* Xn = X + (long long)n * xStride;

    __shared__ float xs[32][36];    // [k][b] padded (even stride for float2 reads)
    __shared__ float ws[32][130];   // [k][c] padded (even stride for float2 reads)
    __shared__ float bs[128];       // per-block sampled bias

    const int tid = threadIdx.x;
    const int b0 = (tid & 7) * 4;
    const int h0 = (tid >> 3) * 8;

    // Sample this block's bias slice: e = n*N + c
    {
        int c = c0 + tid;
        float eps = tf_normal(bk0, bk1, (unsigned)(n * N + c));
        bs[tid] = fmaf(eps, expf(vb[c]), mub[c]);
    }

    unsigned long long acc[4][4];
#pragma unroll
    for (int i = 0; i < 4; i++)
#pragma unroll
        for (int j = 0; j < 4; j++) acc[i][j] = 0ull;

    // eps index base for W: e = ((n*N + c) * K) + k   (max 78.6M < 2^32)
    const unsigned ebase = (unsigned)(((unsigned)(n * N + c0)) * (unsigned)K);

    for (int k0 = 0; k0 < K; k0 += 32) {
        // ---- x tile: 32 k-rows x 32 b (each thread 2 float4) ----
        {
            int idx = tid;
#pragma unroll
            for (int t = 0; t < 2; t++) {
                int r = idx >> 3, c4 = idx & 7;     // r = batch row, c4 = k quad
                float4 xv = *reinterpret_cast<const float4*>(Xn + r * K + k0 + c4 * 4);
                xs[c4 * 4 + 0][r] = xv.x; xs[c4 * 4 + 1][r] = xv.y;
                xs[c4 * 4 + 2][r] = xv.z; xs[c4 * 4 + 3][r] = xv.w;
                idx += 128;
            }
        }
        // ---- generate W tile: 128 c x 32 k = 2048 float2 pairs, 16/thread ----
#pragma unroll 2
        for (int it = 0; it < 16; it++) {
            int p  = it * 128 + tid;
            int cl = p >> 4;                 // local c row
            int kk = (p & 15) * 2;           // even k within tile
            int off = (c0 + cl) * K + k0 + kk;
            unsigned e = ebase + (unsigned)(cl * K + k0 + kk);
            float r0 = tf_normal(wk0, wk1, e);
            float r1 = tf_normal(wk0, wk1, e + 1u);
            float2 m  = *reinterpret_cast<const float2*>(mu + off);
            float2 sv = *reinterpret_cast<const float2*>(s + off);
            ws[kk][cl]     = fmaf(r0, sv.x, m.x);
            ws[kk + 1][cl] = fmaf(r1, sv.y, m.y);
        }
        __syncthreads();

        // ---- FMA: packed f32x2, 16 FFMA2 per kk ----
#pragma unroll 8
        for (int kk = 0; kk < 32; kk++) {
            float2 xa = *reinterpret_cast<const float2*>(&xs[kk][b0]);
            float2 xb = *reinterpret_cast<const float2*>(&xs[kk][b0 + 2]);
            unsigned long long xd[4], wd[4];
            xd[0] = pack_dup(xa.x); xd[1] = pack_dup(xa.y);
            xd[2] = pack_dup(xb.x); xd[3] = pack_dup(xb.y);
#pragma unroll
            for (int j = 0; j < 4; j++)
                wd[j] = *reinterpret_cast<const unsigned long long*>(&ws[kk][h0 + 2 * j]);
#pragma unroll
            for (int i = 0; i < 4; i++)
#pragma unroll
                for (int j = 0; j < 4; j++)
                    acc[i][j] = ffma2(xd[i], wd[j], acc[i][j]);
        }
        __syncthreads();
    }

    // ---- epilogue: bias + (relu) + store ----
#pragma unroll
    for (int j = 0; j < 4; j++) {
        float bj0 = bs[h0 + 2 * j];
        float bj1 = bs[h0 + 2 * j + 1];
#pragma unroll
        for (int i = 0; i < 4; i++) {
            float2 v = unpack2(acc[i][j]);
            v.x += bj0; v.y += bj1;
            if (RELU) { v.x = fmaxf(v.x, 0.0f); v.y = fmaxf(v.y, 0.0f); }
            *reinterpret_cast<float2*>(
                Out + ((long long)n * BATCH + (b0 + i)) * N + c0 + h0 + 2 * j) = v;
        }
    }
}

// -------------------- host-side threefry for subkey derivation --------------------
static inline unsigned h_rotl(unsigned x, int r) { return (x << r) | (x >> (32 - r)); }
static void h_tf2x32(unsigned k0, unsigned k1, unsigned x0, unsigned x1,
                     unsigned& o0, unsigned& o1)
{
    const unsigned ks2 = k0 ^ k1 ^ 0x1BD11BDAu;
    x0 += k0; x1 += k1;
    static const int R[2][4] = {{13, 15, 26, 6}, {17, 29, 16, 24}};
    const unsigned ks[3] = {k0, k1, ks2};
    for (int g = 0; g < 5; g++) {
        for (int r = 0; r < 4; r++) {
            x0 += x1; x1 = h_rotl(x1, R[g & 1][r]); x1 ^= x0;
        }
        x0 += ks[(g + 1) % 3];
        x1 += ks[(g + 2) % 3] + (unsigned)(g + 1);
    }
    o0 = x0; o1 = x1;
}

extern "C" void kernel_launch(void* const* d_in, const int* in_sizes, int n_in,
                              void* d_out, int out_size)
{
    const float* x    = (const float*)d_in[0];
    const float* muW1 = (const float*)d_in[1];
    const float* mub1 = (const float*)d_in[2];
    const float* muW2 = (const float*)d_in[3];
    const float* mub2 = (const float*)d_in[4];
    const float* vW1  = (const float*)d_in[5];
    const float* vb1  = (const float*)d_in[6];
    const float* vW2  = (const float*)d_in[7];
    const float* vb2  = (const float*)d_in[8];
    float* out = (float*)d_out;

    // split(key(42), 4): child i = threefry2x32((0,42),(0,i))
    unsigned keys[4][2];
    for (unsigned i = 0; i < 4; i++)
        h_tf2x32(0u, 42u, 0u, i, keys[i][0], keys[i][1]);

    float *sW1, *sW2, *H;
    cudaGetSymbolAddress((void**)&sW1, g_sW1);
    cudaGetSymbolAddress((void**)&sW2, g_sW2);
    cudaGetSymbolAddress((void**)&H,   g_H);

    prep_kernel<<<(DH * DIN + 255) / 256, 256>>>(vW1, vW2);

    // layer 1: h = relu(x @ W1^T + b1), W1 sampled on the fly
    fused_kernel<DIN, DH, true><<<dim3(NS, DH / 128), 128>>>(
        x, 0LL, muW1, sW1, mub1, vb1, H,
        keys[0][0], keys[0][1], keys[1][0], keys[1][1]);

    // layer 2: y = h @ W2^T + b2, W2 sampled on the fly
    fused_kernel<DH, DOUT, false><<<dim3(NS, DOUT / 128), 128>>>(
        H, (long long)(BATCH * DH), muW2, sW2, mub2, vb2, out,
        keys[2][0], keys[2][1], keys[3][0], keys[3][1]);
}

// round 3
// speedup vs baseline: 1.2318x; 1.2173x over previous
#include <cuda_runtime.h>
#include <cuda_bf16.h>

#define NS    150
#define BATCH 32
#define DIN   1024
#define DH    512
#define DOUT  256

// -------------------- scratch (no cudaMalloc allowed) --------------------
__device__ float g_sW1[DH * DIN];        // exp(v_W1), sample-invariant
__device__ float g_sW2[DOUT * DH];       // exp(v_W2)
__device__ float g_H[NS * BATCH * DH];   // hidden activations

// -------------------- threefry2x32 (JAX-exact, frozen) --------------------
__device__ __forceinline__ void tf2x32(unsigned k0, unsigned k1,
                                       unsigned x0, unsigned x1,
                                       unsigned& o0, unsigned& o1)
{
    const unsigned ks2 = k0 ^ k1 ^ 0x1BD11BDAu;
    x0 += k0; x1 += k1;
#define TF_RND(r) { x0 += x1; x1 = __funnelshift_l(x1, x1, (r)); x1 ^= x0; }
    TF_RND(13) TF_RND(15) TF_RND(26) TF_RND(6)   x0 += k1;  x1 += ks2 + 1u;
    TF_RND(17) TF_RND(29) TF_RND(16) TF_RND(24)  x0 += ks2; x1 += k0  + 2u;
    TF_RND(13) TF_RND(15) TF_RND(26) TF_RND(6)   x0 += k0;  x1 += k1  + 3u;
    TF_RND(17) TF_RND(29) TF_RND(16) TF_RND(24)  x0 += k1;  x1 += ks2 + 4u;
    TF_RND(13) TF_RND(15) TF_RND(26) TF_RND(6)   x0 += ks2; x1 += k0  + 5u;
#undef TF_RND
    o0 = x0; o1 = x1;
}

// erfinv path: bits -> uniform(lo,1) -> sqrt(2)*erfinv. Fast log via MUFU
// (tolerance 1e-3; w-error ~1e-5 is invisible after the poly).
__device__ __forceinline__ float bits_to_normal(unsigned bits)
{
    float f = __uint_as_float((bits >> 9) | 0x3f800000u) - 1.0f;
    float x = fmaf(f, 2.0f, -0.99999994f);

    float w = -__logf(fmaf(-x, x, 1.0f));
    float p;
    if (w < 5.0f) {
        w -= 2.5f;
        p = 2.81022636e-08f;
        p = fmaf(p, w, 3.43273939e-07f);
        p = fmaf(p, w, -3.5233877e-06f);
        p = fmaf(p, w, -4.39150654e-06f);
        p = fmaf(p, w, 0.00021858087f);
        p = fmaf(p, w, -0.00125372503f);
        p = fmaf(p, w, -0.00417768164f);
        p = fmaf(p, w, 0.246640727f);
        p = fmaf(p, w, 1.50140941f);
    } else {
        w = sqrtf(w) - 3.0f;
        p = -0.000200214257f;
        p = fmaf(p, w, 0.000100950558f);
        p = fmaf(p, w, 0.00134934322f);
        p = fmaf(p, w, -0.00367342844f);
        p = fmaf(p, w, 0.00573950773f);
        p = fmaf(p, w, -0.0076224613f);
        p = fmaf(p, w, 0.00943887047f);
        p = fmaf(p, w, 1.00167406f);
        p = fmaf(p, w, 2.83297682f);
    }
    return 1.41421356237f * (p * x);
}

__device__ __forceinline__ float tf_normal(unsigned k0, unsigned k1, unsigned e)
{
    unsigned o0, o1;
    tf2x32(k0, k1, 0u, e, o0, o1);
    return bits_to_normal(o0 ^ o1);
}

// 4 interleaved threefry chains (counters e..e+3) -> ILP 4 on the ALU chain.
__device__ __forceinline__ void tf_normal4(unsigned k0, unsigned k1, unsigned e,
                                           float r[4])
{
    const unsigned ks2 = k0 ^ k1 ^ 0x1BD11BDAu;
    unsigned a[4], b[4];
#pragma unroll
    for (int i = 0; i < 4; i++) { a[i] = k0; b[i] = (e + (unsigned)i) + k1; }

#define TF_R4(rr) _Pragma("unroll") \
    for (int i = 0; i < 4; i++) { a[i] += b[i]; b[i] = __funnelshift_l(b[i], b[i], (rr)); b[i] ^= a[i]; }
#define TF_INJ4(ka, kb, g) _Pragma("unroll") \
    for (int i = 0; i < 4; i++) { a[i] += (ka); b[i] += (kb) + (g); }

    TF_R4(13) TF_R4(15) TF_R4(26) TF_R4(6)   TF_INJ4(k1,  ks2, 1u)
    TF_R4(17) TF_R4(29) TF_R4(16) TF_R4(24)  TF_INJ4(ks2, k0,  2u)
    TF_R4(13) TF_R4(15) TF_R4(26) TF_R4(6)   TF_INJ4(k0,  k1,  3u)
    TF_R4(17) TF_R4(29) TF_R4(16) TF_R4(24)  TF_INJ4(k1,  ks2, 4u)
    TF_R4(13) TF_R4(15) TF_R4(26) TF_R4(6)   TF_INJ4(ks2, k0,  5u)
#undef TF_R4
#undef TF_INJ4

#pragma unroll
    for (int i = 0; i < 4; i++) r[i] = bits_to_normal(a[i] ^ b[i]);
}

// -------------------- packed f32x2 helpers (sm_100+ PTX) --------------------
__device__ __forceinline__ unsigned long long pack_dup(float a)
{
    unsigned long long d;
    unsigned r = __float_as_uint(a);
    asm("mov.b64 %0, {%1, %1};" : "=l"(d) : "r"(r));
    return d;
}
__device__ __forceinline__ unsigned long long ffma2(unsigned long long a,
                                                    unsigned long long b,
                                                    unsigned long long c)
{
    unsigned long long d;
    asm("fma.rn.f32x2 %0, %1, %2, %3;" : "=l"(d) : "l"(a), "l"(b), "l"(c));
    return d;
}
__device__ __forceinline__ float2 unpack2(unsigned long long d)
{
    unsigned lo, hi;
    asm("mov.b64 {%0, %1}, %2;" : "=r"(lo), "=r"(hi) : "l"(d));
    return make_float2(__uint_as_float(lo), __uint_as_float(hi));
}

// -------------------- exp(v_W) precompute (bit-identical expf) --------------------
__global__ __launch_bounds__(256) void prep_kernel(const float* __restrict__ vW1,
                                                   const float* __restrict__ vW2)
{
    int i = blockIdx.x * 256 + threadIdx.x;
    if (i < DH * DIN)  g_sW1[i] = expf(vW1[i]);
    if (i < DOUT * DH) g_sW2[i] = expf(vW2[i]);
}

// -------------------- fused sample-and-GEMM --------------------
// Out[n][b][c] = act( bias_n[c] + sum_k X[n][b][k] * (mu[c][k] + eps(n,c,k)*s[c][k]) )
// block = (n, CTILE-wide c tile), 128 threads.
template<int K, int N, int CTILE, bool RELU>
__global__ __launch_bounds__(128) void fused_kernel(
    const float* __restrict__ X, long long xStride,
    const float* __restrict__ mu, const float* __restrict__ s,
    const float* __restrict__ mub, const float* __restrict__ vb,
    float* __restrict__ Out,
    unsigned wk0, unsigned wk1, unsigned bk0, unsigned bk1)
{
    constexpr int HALVES = 128 / CTILE;       // k-splits of a row per thread
    constexpr int KSEG   = 32 / HALVES;       // k values generated per thread
    constexpr int CG     = CTILE / 16;        // c cols per thread (FMA)
    constexpr int CP     = CG / 2;            // f32x2 pairs per thread col dim

    const int n  = blockIdx.x;
    const int c0 = blockIdx.y * CTILE;
    const float* Xn = X + (long long)n * xStride;

    __shared__ float xs[32][36];          // [k][b] padded
    __shared__ float ws[32][CTILE + 2];   // [k][c] padded (even stride)
    __shared__ float bs[CTILE];

    const int tid = threadIdx.x;
    const int b0 = (tid & 7) * 4;
    const int h0 = (tid >> 3) * CG;

    // gen mapping: thread owns c-row `gr`, k segment [gk0, gk0+KSEG)
    const int gr  = tid % CTILE;
    const int gk0 = (tid / CTILE) * KSEG;

    // per-block sampled bias: e = n*N + c
    if (tid < CTILE) {
        int c = c0 + tid;
        float eps = tf_normal(bk0, bk1, (unsigned)(n * N + c));
        bs[tid] = fmaf(eps, expf(vb[c]), mub[c]);
    }

    unsigned long long acc[4][CP];
#pragma unroll
    for (int i = 0; i < 4; i++)
#pragma unroll
        for (int j = 0; j < CP; j++) acc[i][j] = 0ull;

    // eps index for W: e = (n*N + c)*K + k  (max 78.6M < 2^32)
    const unsigned erow = (unsigned)(n * N + c0 + gr) * (unsigned)K + (unsigned)gk0;
    const float* muRow = mu + (long long)(c0 + gr) * K + gk0;
    const float* sRow  = s  + (long long)(c0 + gr) * K + gk0;

    for (int k0 = 0; k0 < K; k0 += 32) {
        // ---- x tile: 32 b x 32 k (each thread 2 float4) ----
        {
            int idx = tid;
#pragma unroll
            for (int t = 0; t < 2; t++) {
                int r = idx >> 3, c4 = idx & 7;
                float4 xv = *reinterpret_cast<const float4*>(Xn + r * K + k0 + c4 * 4);
                xs[c4 * 4 + 0][r] = xv.x; xs[c4 * 4 + 1][r] = xv.y;
                xs[c4 * 4 + 2][r] = xv.z; xs[c4 * 4 + 3][r] = xv.w;
                idx += 128;
            }
        }
        // ---- generate W tile: thread = row gr, k in [gk0, gk0+KSEG), quads of 4 ----
#pragma unroll
        for (int q = 0; q < KSEG / 4; q++) {
            int kk = gk0 + q * 4;
            float r4[4];
            tf_normal4(wk0, wk1, erow + (unsigned)(k0 + q * 4), r4);
            float4 m  = *reinterpret_cast<const float4*>(muRow + k0 + q * 4);
            float4 sv = *reinterpret_cast<const float4*>(sRow  + k0 + q * 4);
            ws[kk + 0][gr] = fmaf(r4[0], sv.x, m.x);
            ws[kk + 1][gr] = fmaf(r4[1], sv.y, m.y);
            ws[kk + 2][gr] = fmaf(r4[2], sv.z, m.z);
            ws[kk + 3][gr] = fmaf(r4[3], sv.w, m.w);
        }
        __syncthreads();

        // ---- FMA: packed f32x2 ----
#pragma unroll 8
        for (int kk = 0; kk < 32; kk++) {
            unsigned long long xd[4], wd[CP];
            xd[0] = pack_dup(xs[kk][b0 + 0]);
            xd[1] = pack_dup(xs[kk][b0 + 1]);
            xd[2] = pack_dup(xs[kk][b0 + 2]);
            xd[3] = pack_dup(xs[kk][b0 + 3]);
#pragma unroll
            for (int j = 0; j < CP; j++)
                wd[j] = *reinterpret_cast<const unsigned long long*>(&ws[kk][h0 + 2 * j]);
#pragma unroll
            for (int i = 0; i < 4; i++)
#pragma unroll
                for (int j = 0; j < CP; j++)
                    acc[i][j] = ffma2(xd[i], wd[j], acc[i][j]);
        }
        __syncthreads();
    }

    // ---- epilogue ----
#pragma unroll
    for (int j = 0; j < CP; j++) {
        float bj0 = bs[h0 + 2 * j];
        float bj1 = bs[h0 + 2 * j + 1];
#pragma unroll
        for (int i = 0; i < 4; i++) {
            float2 v = unpack2(acc[i][j]);
            v.x += bj0; v.y += bj1;
            if (RELU) { v.x = fmaxf(v.x, 0.0f); v.y = fmaxf(v.y, 0.0f); }
            *reinterpret_cast<float2*>(
                Out + ((long long)n * BATCH + (b0 + i)) * N + c0 + h0 + 2 * j) = v;
        }
    }
}

// -------------------- host-side threefry for subkey derivation --------------------
static inline unsigned h_rotl(unsigned x, int r) { return (x << r) | (x >> (32 - r)); }
static void h_tf2x32(unsigned k0, unsigned k1, unsigned x0, unsigned x1,
                     unsigned& o0, unsigned& o1)
{
    const unsigned ks2 = k0 ^ k1 ^ 0x1BD11BDAu;
    x0 += k0; x1 += k1;
    static const int R[2][4] = {{13, 15, 26, 6}, {17, 29, 16, 24}};
    const unsigned ks[3] = {k0, k1, ks2};
    for (int g = 0; g < 5; g++) {
        for (int r = 0; r < 4; r++) {
            x0 += x1; x1 = h_rotl(x1, R[g & 1][r]); x1 ^= x0;
        }
        x0 += ks[(g + 1) % 3];
        x1 += ks[(g + 2) % 3] + (unsigned)(g + 1);
    }
    o0 = x0; o1 = x1;
}

extern "C" void kernel_launch(void* const* d_in, const int* in_sizes, int n_in,
                              void* d_out, int out_size)
{
    const float* x    = (const float*)d_in[0];
    const float* muW1 = (const float*)d_in[1];
    const float* mub1 = (const float*)d_in[2];
    const float* muW2 = (const float*)d_in[3];
    const float* mub2 = (const float*)d_in[4];
    const float* vW1  = (const float*)d_in[5];
    const float* vb1  = (const float*)d_in[6];
    const float* vW2  = (const float*)d_in[7];
    const float* vb2  = (const float*)d_in[8];
    float* out = (float*)d_out;

    unsigned keys[4][2];
    for (unsigned i = 0; i < 4; i++)
        h_tf2x32(0u, 42u, 0u, i, keys[i][0], keys[i][1]);

    float *sW1, *sW2, *H;
    cudaGetSymbolAddress((void**)&sW1, g_sW1);
    cudaGetSymbolAddress((void**)&sW2, g_sW2);
    cudaGetSymbolAddress((void**)&H,   g_H);

    prep_kernel<<<(DH * DIN + 255) / 256, 256>>>(vW1, vW2);

    // layer 1: h = relu(x @ W1^T + b1), CTILE=128 -> grid 150x4
    fused_kernel<DIN, DH, 128, true><<<dim3(NS, DH / 128), 128>>>(
        x, 0LL, muW1, sW1, mub1, vb1, H,
        keys[0][0], keys[0][1], keys[1][0], keys[1][1]);

    // layer 2: y = h @ W2^T + b2, CTILE=64 -> grid 150x4 (occupancy fix)
    fused_kernel<DH, DOUT, 64, false><<<dim3(NS, DOUT / 64), 128>>>(
        H, (long long)(BATCH * DH), muW2, sW2, mub2, vb2, out,
        keys[2][0], keys[2][1], keys[3][0], keys[3][1]);
}